// round 1
// baseline (speedup 1.0000x reference)
#include <cuda_runtime.h>
#include <cuda_bf16.h>
#include <math.h>

// Problem constants
#define BB 2
#define SS 2048
#define DD 2048
#define HH 16
#define QLORA 1536
#define KVLORA 512
#define DNOPE 128
#define DROPE 64
#define DVV 128
#define DQK 192
#define MTOT (BB*SS)            // 4096 total rows
#define QW (HH*DQK)             // 3072
#define KVBW (HH*(DNOPE+DVV))   // 4096
#define KVW (KVLORA+DROPE)      // 576
#define OW (HH*DVV)             // 2048

// ---------------- scratch (static device globals; no allocation) ----------------
__device__ float g_qa  [(size_t)MTOT * QLORA];   // 25.2 MB
__device__ float g_q   [(size_t)MTOT * QW];      // 50.3 MB
__device__ float g_kv  [(size_t)MTOT * KVW];     //  9.4 MB
__device__ float g_kvn [(size_t)MTOT * KVLORA];  //  8.4 MB
__device__ float g_kvb [(size_t)MTOT * KVBW];    // 67.1 MB
__device__ float g_attn[(size_t)MTOT * OW];      // 33.6 MB

// ---------------- generic NT SGEMM: C[m,n] = sum_k A[m,k]*B[n,k] ----------------
// A: MxK row-major, B: NxK row-major, C: MxN row-major.
// 128x128 tile, BK=16, 256 threads, 8x8 per thread.
#define GBM 128
#define GBN 128
#define GBK 16

__global__ __launch_bounds__(256) void sgemm_nt(
    const float* __restrict__ A, const float* __restrict__ B,
    float* __restrict__ C, int M, int N, int K)
{
    __shared__ float As[GBK][GBM];
    __shared__ float Bs[GBK][GBN];

    const int tid = threadIdx.x;
    const int tx = tid & 15;          // 0..15 -> n
    const int ty = tid >> 4;          // 0..15 -> m
    const int m0 = blockIdx.y * GBM;
    const int n0 = blockIdx.x * GBN;

    const int lr = tid >> 2;          // 0..63 (row within half-tile)
    const int lc = tid & 3;           // 0..3  (float4 slot along k)

    float acc[8][8];
#pragma unroll
    for (int i = 0; i < 8; i++)
#pragma unroll
        for (int j = 0; j < 8; j++) acc[i][j] = 0.f;

    for (int k0 = 0; k0 < K; k0 += GBK) {
#pragma unroll
        for (int s = 0; s < 2; s++) {
            int r = lr + s * 64;
            int gm = m0 + r;
            float4 v = make_float4(0.f, 0.f, 0.f, 0.f);
            if (gm < M)
                v = *(const float4*)(A + (size_t)gm * K + k0 + lc * 4);
            As[lc*4+0][r] = v.x; As[lc*4+1][r] = v.y;
            As[lc*4+2][r] = v.z; As[lc*4+3][r] = v.w;
        }
#pragma unroll
        for (int s = 0; s < 2; s++) {
            int r = lr + s * 64;
            int gn = n0 + r;
            float4 v = make_float4(0.f, 0.f, 0.f, 0.f);
            if (gn < N)
                v = *(const float4*)(B + (size_t)gn * K + k0 + lc * 4);
            Bs[lc*4+0][r] = v.x; Bs[lc*4+1][r] = v.y;
            Bs[lc*4+2][r] = v.z; Bs[lc*4+3][r] = v.w;
        }
        __syncthreads();

#pragma unroll
        for (int k = 0; k < GBK; k++) {
            float ra[8], rb[8];
            *(float4*)(ra)     = *(const float4*)&As[k][ty*8];
            *(float4*)(ra + 4) = *(const float4*)&As[k][ty*8+4];
            *(float4*)(rb)     = *(const float4*)&Bs[k][tx*8];
            *(float4*)(rb + 4) = *(const float4*)&Bs[k][tx*8+4];
#pragma unroll
            for (int i = 0; i < 8; i++)
#pragma unroll
                for (int j = 0; j < 8; j++)
                    acc[i][j] = fmaf(ra[i], rb[j], acc[i][j]);
        }
        __syncthreads();
    }

#pragma unroll
    for (int i = 0; i < 8; i++) {
        int gm = m0 + ty * 8 + i;
        if (gm >= M) continue;
#pragma unroll
        for (int j4 = 0; j4 < 2; j4++) {
            int gn = n0 + tx * 8 + j4 * 4;
            if (gn < N) {   // N is always a multiple of 4 here
                float4 v = make_float4(acc[i][j4*4+0], acc[i][j4*4+1],
                                       acc[i][j4*4+2], acc[i][j4*4+3]);
                *(float4*)(C + (size_t)gm * N + gn) = v;
            }
        }
    }
}

// ---------------- RMSNorm (row-wise): out = in * rsqrt(mean(in^2)+eps) * w ------
__global__ __launch_bounds__(256) void rmsnorm_kernel(
    const float* __restrict__ in, int instride,
    const float* __restrict__ w,
    float* __restrict__ out, int outstride, int width)
{
    const int row = blockIdx.x;
    const float* rp = in + (size_t)row * instride;
    float ss = 0.f;
    for (int i = threadIdx.x; i < width; i += 256) {
        float v = rp[i];
        ss += v * v;
    }
    __shared__ float red[256];
    red[threadIdx.x] = ss;
    __syncthreads();
    for (int s = 128; s > 0; s >>= 1) {
        if (threadIdx.x < s) red[threadIdx.x] += red[threadIdx.x + s];
        __syncthreads();
    }
    const float scale = rsqrtf(red[0] / (float)width + 1e-6f);
    float* op = out + (size_t)row * outstride;
    for (int i = threadIdx.x; i < width; i += 256)
        op[i] = rp[i] * scale * w[i];
}

// ---------------- RoPE ----------------------------------------------------------
// q layout: [m, h*192 + d], rope applied to d in [128,192), pairs (2i, 2i+1)
__global__ void rope_q_kernel(float* __restrict__ q, const float* __restrict__ fc)
{
    int idx = blockIdx.x * blockDim.x + threadIdx.x;
    const int total = MTOT * HH * (DROPE / 2);
    if (idx >= total) return;
    int m = idx >> 9;              // /(16*32)
    int r = idx & 511;
    int h = r >> 5;
    int i = r & 31;
    int s = m & (SS - 1);
    float c  = fc[s * 64 + i * 2];
    float sn = fc[s * 64 + i * 2 + 1];
    float* p = q + (size_t)m * QW + h * DQK + DNOPE + i * 2;
    float re = p[0], im = p[1];
    p[0] = re * c - im * sn;
    p[1] = re * sn + im * c;
}

// kv layout: [m, 576], rope applied to d in [512,576)
__global__ void rope_kpe_kernel(float* __restrict__ kv, const float* __restrict__ fc)
{
    int idx = blockIdx.x * blockDim.x + threadIdx.x;
    const int total = MTOT * (DROPE / 2);
    if (idx >= total) return;
    int m = idx >> 5;
    int i = idx & 31;
    int s = m & (SS - 1);
    float c  = fc[s * 64 + i * 2];
    float sn = fc[s * 64 + i * 2 + 1];
    float* p = kv + (size_t)m * KVW + KVLORA + i * 2;
    float re = p[0], im = p[1];
    p[0] = re * c - im * sn;
    p[1] = re * sn + im * c;
}

// ---------------- Flash attention (causal, fp32) --------------------------------
// grid: (32 q-tiles, 16 heads, 2 batch); 256 threads; BM=BN=64.
// q:   [4096, 3072]  (m, h*192+d)
// kvb: [4096, 4096]  (m, h*256 + d)   d<128: k_nope, d>=128: v
// kvp: [4096, 576]   k_pe at [512,576) shared across heads
// out: [4096, 2048]  (m, h*128+d)
#define ATT_SMEM ((192*64 + 192*64 + 64*128 + 64*64) * 4)

__global__ __launch_bounds__(256) void mla_attn_kernel(
    const float* __restrict__ q, const float* __restrict__ kvb,
    const float* __restrict__ kvp, float* __restrict__ out)
{
    extern __shared__ float sm[];
    float* Qt = sm;                // [192][64]   (k-major, transposed)
    float* Kt = sm + 192 * 64;     // [192][64]
    float* Vs = Kt + 192 * 64;     // [64][128]
    float* Ps = Vs + 64 * 128;     // [64][64]

    const int qt = blockIdx.x;
    const int h  = blockIdx.y;
    const int b  = blockIdx.z;
    const int tid = threadIdx.x;
    const int tx = tid & 15;       // key cols (4 each)
    const int ty = tid >> 4;       // query rows (4 each)
    const int m0 = qt * 64;
    const int rowbase = b * SS;

    // Load Q tile transposed: Qt[k][r]
    for (int i = tid; i < 64 * 48; i += 256) {
        int r = i / 48, c4 = i % 48;
        float4 v = *(const float4*)(q + (size_t)(rowbase + m0 + r) * QW + h * DQK + c4 * 4);
        Qt[(c4*4+0)*64 + r] = v.x; Qt[(c4*4+1)*64 + r] = v.y;
        Qt[(c4*4+2)*64 + r] = v.z; Qt[(c4*4+3)*64 + r] = v.w;
    }

    float mi[4], li[4], oacc[4][8];
#pragma unroll
    for (int i = 0; i < 4; i++) {
        mi[i] = -INFINITY; li[i] = 0.f;
#pragma unroll
        for (int j = 0; j < 8; j++) oacc[i][j] = 0.f;
    }
    const float scale = 0.07216878364870323f;  // 1/sqrt(192)

    for (int t = 0; t <= qt; t++) {
        const int n0 = t * 64;
        __syncthreads();   // protect Kt/Vs/Ps from previous iteration's readers

        // K nope -> Kt[k][r], k in [0,128)
        for (int i = tid; i < 64 * 32; i += 256) {
            int r = i / 32, c4 = i % 32;
            float4 v = *(const float4*)(kvb + (size_t)(rowbase + n0 + r) * KVBW + h * 256 + c4 * 4);
            Kt[(c4*4+0)*64 + r] = v.x; Kt[(c4*4+1)*64 + r] = v.y;
            Kt[(c4*4+2)*64 + r] = v.z; Kt[(c4*4+3)*64 + r] = v.w;
        }
        // K pe -> Kt[k][r], k in [128,192)
        for (int i = tid; i < 64 * 16; i += 256) {
            int r = i / 16, c4 = i % 16;
            float4 v = *(const float4*)(kvp + (size_t)(rowbase + n0 + r) * KVW + KVLORA + c4 * 4);
            Kt[(128+c4*4+0)*64 + r] = v.x; Kt[(128+c4*4+1)*64 + r] = v.y;
            Kt[(128+c4*4+2)*64 + r] = v.z; Kt[(128+c4*4+3)*64 + r] = v.w;
        }
        // V tile (row-major)
        for (int i = tid; i < 64 * 32; i += 256) {
            int r = i / 32, c4 = i % 32;
            ((float4*)(Vs + r * 128))[c4] =
                *(const float4*)(kvb + (size_t)(rowbase + n0 + r) * KVBW + h * 256 + 128 + c4 * 4);
        }
        __syncthreads();

        // scores: s[i][j] = Q[ty*4+i] . K[tx*4+j]
        float s[4][4];
#pragma unroll
        for (int i = 0; i < 4; i++)
#pragma unroll
            for (int j = 0; j < 4; j++) s[i][j] = 0.f;

#pragma unroll 4
        for (int k = 0; k < DQK; k++) {
            float4 a  = *(const float4*)(Qt + k * 64 + ty * 4);
            float4 bb = *(const float4*)(Kt + k * 64 + tx * 4);
            s[0][0] = fmaf(a.x, bb.x, s[0][0]); s[0][1] = fmaf(a.x, bb.y, s[0][1]);
            s[0][2] = fmaf(a.x, bb.z, s[0][2]); s[0][3] = fmaf(a.x, bb.w, s[0][3]);
            s[1][0] = fmaf(a.y, bb.x, s[1][0]); s[1][1] = fmaf(a.y, bb.y, s[1][1]);
            s[1][2] = fmaf(a.y, bb.z, s[1][2]); s[1][3] = fmaf(a.y, bb.w, s[1][3]);
            s[2][0] = fmaf(a.z, bb.x, s[2][0]); s[2][1] = fmaf(a.z, bb.y, s[2][1]);
            s[2][2] = fmaf(a.z, bb.z, s[2][2]); s[2][3] = fmaf(a.z, bb.w, s[2][3]);
            s[3][0] = fmaf(a.w, bb.x, s[3][0]); s[3][1] = fmaf(a.w, bb.y, s[3][1]);
            s[3][2] = fmaf(a.w, bb.z, s[3][2]); s[3][3] = fmaf(a.w, bb.w, s[3][3]);
        }

        const bool diag = (t == qt);
#pragma unroll
        for (int i = 0; i < 4; i++) {
#pragma unroll
            for (int j = 0; j < 4; j++) {
                s[i][j] *= scale;
                if (diag && (n0 + tx * 4 + j > m0 + ty * 4 + i)) s[i][j] = -INFINITY;
            }
            // row-max across this thread then across the 16-lane tx group
            float rm = fmaxf(fmaxf(s[i][0], s[i][1]), fmaxf(s[i][2], s[i][3]));
#pragma unroll
            for (int off = 1; off < 16; off <<= 1)
                rm = fmaxf(rm, __shfl_xor_sync(0xffffffffu, rm, off));
            float mnew = fmaxf(mi[i], rm);
            float p0 = __expf(s[i][0] - mnew);
            float p1 = __expf(s[i][1] - mnew);
            float p2 = __expf(s[i][2] - mnew);
            float p3 = __expf(s[i][3] - mnew);
            float rs = p0 + p1 + p2 + p3;
#pragma unroll
            for (int off = 1; off < 16; off <<= 1)
                rs += __shfl_xor_sync(0xffffffffu, rs, off);
            float alpha = __expf(mi[i] - mnew);
            li[i] = li[i] * alpha + rs;
            mi[i] = mnew;
#pragma unroll
            for (int j = 0; j < 8; j++) oacc[i][j] *= alpha;
            float* pr = Ps + (ty * 4 + i) * 64 + tx * 4;
            pr[0] = p0; pr[1] = p1; pr[2] = p2; pr[3] = p3;
        }
        __syncthreads();

        // O += P @ V   (64x64 * 64x128), thread owns rows ty*4..+3, cols tx*8..+7
#pragma unroll 4
        for (int kk = 0; kk < 64; kk++) {
            float4 v0 = *(const float4*)(Vs + kk * 128 + tx * 8);
            float4 v1 = *(const float4*)(Vs + kk * 128 + tx * 8 + 4);
#pragma unroll
            for (int i = 0; i < 4; i++) {
                float pp = Ps[(ty * 4 + i) * 64 + kk];
                oacc[i][0] = fmaf(pp, v0.x, oacc[i][0]);
                oacc[i][1] = fmaf(pp, v0.y, oacc[i][1]);
                oacc[i][2] = fmaf(pp, v0.z, oacc[i][2]);
                oacc[i][3] = fmaf(pp, v0.w, oacc[i][3]);
                oacc[i][4] = fmaf(pp, v1.x, oacc[i][4]);
                oacc[i][5] = fmaf(pp, v1.y, oacc[i][5]);
                oacc[i][6] = fmaf(pp, v1.z, oacc[i][6]);
                oacc[i][7] = fmaf(pp, v1.w, oacc[i][7]);
            }
        }
    }

    // epilogue: normalize and store
#pragma unroll
    for (int i = 0; i < 4; i++) {
        float inv = 1.f / li[i];
        size_t gm = (size_t)(rowbase + m0 + ty * 4 + i);
        float* op = out + gm * OW + h * DVV + tx * 8;
        float4 w0 = make_float4(oacc[i][0]*inv, oacc[i][1]*inv, oacc[i][2]*inv, oacc[i][3]*inv);
        float4 w1 = make_float4(oacc[i][4]*inv, oacc[i][5]*inv, oacc[i][6]*inv, oacc[i][7]*inv);
        *(float4*)(op)     = w0;
        *(float4*)(op + 4) = w1;
    }
}

// ---------------- host launcher --------------------------------------------------
static float* sym_addr(const void* sym) {
    void* p = nullptr;
    cudaGetSymbolAddress(&p, sym);
    return (float*)p;
}

extern "C" void kernel_launch(void* const* d_in, const int* in_sizes, int n_in,
                              void* d_out, int out_size)
{
    const float* x        = (const float*)d_in[0];
    // d_in[1] = start_pos (always 0 here)
    const float* fc       = (const float*)d_in[2];
    const float* wq_a     = (const float*)d_in[3];
    const float* q_norm_w = (const float*)d_in[4];
    const float* wq_b     = (const float*)d_in[5];
    const float* wkv_a    = (const float*)d_in[6];
    const float* kv_norm_w= (const float*)d_in[7];
    const float* wkv_b    = (const float*)d_in[8];
    const float* wo       = (const float*)d_in[9];
    float* out = (float*)d_out;

    float* qa   = sym_addr(g_qa);
    float* qbuf = sym_addr(g_q);
    float* kv   = sym_addr(g_kv);
    float* kvn  = sym_addr(g_kvn);
    float* kvb  = sym_addr(g_kvb);
    float* attn = sym_addr(g_attn);

    // q_a = x @ wq_a^T   [4096,1536]
    sgemm_nt<<<dim3(QLORA/GBN, MTOT/GBM), 256>>>(x, wq_a, qa, MTOT, QLORA, DD);
    // rmsnorm(q_a) in place
    rmsnorm_kernel<<<MTOT, 256>>>(qa, QLORA, q_norm_w, qa, QLORA, QLORA);
    // q = qn @ wq_b^T    [4096,3072]
    sgemm_nt<<<dim3(QW/GBN, MTOT/GBM), 256>>>(qa, wq_b, qbuf, MTOT, QW, QLORA);
    // rope on q_pe
    {
        int total = MTOT * HH * (DROPE / 2);
        rope_q_kernel<<<(total + 255) / 256, 256>>>(qbuf, fc);
    }
    // kv = x @ wkv_a^T   [4096,576]
    sgemm_nt<<<dim3((KVW + GBN - 1) / GBN, MTOT/GBM), 256>>>(x, wkv_a, kv, MTOT, KVW, DD);
    // rope on k_pe
    {
        int total = MTOT * (DROPE / 2);
        rope_kpe_kernel<<<(total + 255) / 256, 256>>>(kv, fc);
    }
    // rmsnorm(kv_c) -> kvn
    rmsnorm_kernel<<<MTOT, 256>>>(kv, KVW, kv_norm_w, kvn, KVLORA, KVLORA);
    // kvb = kvn @ wkv_b^T  [4096,4096]
    sgemm_nt<<<dim3(KVBW/GBN, MTOT/GBM), 256>>>(kvn, wkv_b, kvb, MTOT, KVBW, KVLORA);

    // attention
    cudaFuncSetAttribute(mla_attn_kernel, cudaFuncAttributeMaxDynamicSharedMemorySize, ATT_SMEM);
    mla_attn_kernel<<<dim3(SS/64, HH, BB), 256, ATT_SMEM>>>(qbuf, kvb, kv, attn);

    // out = attn @ wo^T   [4096,2048]
    sgemm_nt<<<dim3(DD/GBN, MTOT/GBM), 256>>>(attn, wo, out, MTOT, DD, OW);
}